// round 17
// baseline (speedup 1.0000x reference)
#include <cuda_runtime.h>
#include <cuda_bf16.h>

#define NATOMS 512
#define NBATCH 16
#define NP 16

// ---- compile-time constants (constexpr repeated-multiply; NO runtime pow) ----
constexpr double RQd = 0.09913776814937592;   // exp(-2*eta*dshf^2)
constexpr double rqp(int n) {
    double r = 1.0;
    for (int i = 0; i < n; ++i) r *= RQd;
    return r;
}
constexpr double L2Ed = 1.4426950408889634;
constexpr double ETAd = 16.0, DSHd = 0.26875;
constexpr double C2d  = -ETAd * L2Ed;

constexpr float RQ4_1 = (float)rqp(4),  RQ4_2 = (float)rqp(8),  RQ4_3 = (float)rqp(12);
constexpr float T1_0  = (float)rqp(1),  T1_1  = (float)rqp(9),
                T1_2  = (float)rqp(17), T1_3  = (float)rqp(25);
constexpr float T2_0  = (float)rqp(3),  T2_1  = (float)rqp(11),
                T2_2  = (float)rqp(19), T2_3  = (float)rqp(27);
constexpr float TC_1 = (float)(-8.0 * C2d * DSHd * 1.0);
constexpr float TC_2 = (float)(-8.0 * C2d * DSHd * 2.0);
constexpr float TC_3 = (float)(-8.0 * C2d * DSHd * 3.0);
constexpr float DD_1 = (float)(16.0 * C2d * DSHd * DSHd * 1.0);
constexpr float DD_2 = (float)(16.0 * C2d * DSHd * DSHd * 4.0);
constexpr float DD_3 = (float)(16.0 * C2d * DSHd * DSHd * 9.0);

// exp(-16*sp^2), sp = 0.9 + 0.26875*p : diagonal (d==0) correction
__constant__ float DIAG[16] = {
    2.3525e-6f, 3.1654e-10f, 4.3761e-15f, 5.8930e-21f,
    7.8650e-28f, 1.0413e-35f, 1.3600e-44f, 0.0f,
    0.0f, 0.0f, 0.0f, 0.0f, 0.0f, 0.0f, 0.0f, 0.0f};

// one element's full update: 4 groups of 4 shifts into acc[16]
__device__ __forceinline__ void aev_element(const float dj, const float zj,
                                            float* __restrict__ acc)
{
    constexpr float RCR       = 5.2f;
    constexpr float PI_OVER_R = 3.14159265358979323846f / 5.2f;
    constexpr float C2 = (float)C2d;
    constexpr float A1 = (float)( 2.0 * ETAd * DSHd * L2Ed);
    constexpr float A0 = (float)(-ETAd * DSHd * DSHd * L2Ed);

    // clamp once; fc(clamped) ~ 0 self-masks d>=RCR; diagonal fixed at store
    const float dg = fminf(dj, RCR);
    float c;
    asm("cos.approx.ftz.f32 %0, %1;" : "=f"(c) : "f"(dg * PI_OVER_R));
    const float w = fmaf(zj, c, zj);              // z*(cos+1); 0.5 at store

    const float u0 = dg - 0.9f;
    float q;
    asm("ex2.approx.ftz.f32 %0, %1;" : "=f"(q) : "f"(fmaf(A1, u0, A0)));
    const float s    = q * q;                     // bounded: dg <= RCR
    const float arg0 = (C2 * u0) * u0;

    float g, G, GQ;
    // k = 0
    asm("ex2.approx.ftz.f32 %0, %1;" : "=f"(g) : "f"(arg0));
    G  = w * g;
    GQ = G * q;
    acc[0] += G;
    acc[1] += GQ;
    acc[2]  = fmaf(G,  s * T1_0, acc[2]);
    acc[3]  = fmaf(GQ, s * T2_0, acc[3]);
    // k = 1
    {
        const float arg = fmaf(TC_1, u0, arg0) + DD_1;
        asm("ex2.approx.ftz.f32 %0, %1;" : "=f"(g) : "f"(arg));
        const float qk = q * RQ4_1;
        G  = w * g;
        GQ = G * qk;
        acc[4] += G;
        acc[5] += GQ;
        acc[6]  = fmaf(G,  s * T1_1, acc[6]);
        acc[7]  = fmaf(GQ, s * T2_1, acc[7]);
    }
    // k = 2
    {
        const float arg = fmaf(TC_2, u0, arg0) + DD_2;
        asm("ex2.approx.ftz.f32 %0, %1;" : "=f"(g) : "f"(arg));
        const float qk = q * RQ4_2;
        G  = w * g;
        GQ = G * qk;
        acc[8]  += G;
        acc[9]  += GQ;
        acc[10]  = fmaf(G,  s * T1_2, acc[10]);
        acc[11]  = fmaf(GQ, s * T2_2, acc[11]);
    }
    // k = 3
    {
        const float arg = fmaf(TC_3, u0, arg0) + DD_3;
        asm("ex2.approx.ftz.f32 %0, %1;" : "=f"(g) : "f"(arg));
        const float qk = q * RQ4_3;
        G  = w * g;
        GQ = G * qk;
        acc[12] += G;
        acc[13] += GQ;
        acc[14]  = fmaf(G,  s * T1_3, acc[14]);
        acc[15]  = fmaf(GQ, s * T2_3, acc[15]);
    }
}

__device__ __forceinline__ void reduce_store(float* __restrict__ acc,
                                             const float zi, float* __restrict__ dst,
                                             const int lane)
{
    const unsigned FULL = 0xffffffffu;
#pragma unroll
    for (int v = 0; v < 8; ++v) {
        const bool hi = (lane & 16);
        const float send = hi ? acc[v] : acc[v + 8];
        const float r = __shfl_xor_sync(FULL, send, 16);
        acc[v] = (hi ? acc[v + 8] : acc[v]) + r;
    }
#pragma unroll
    for (int v = 0; v < 4; ++v) {
        const bool hi = (lane & 8);
        const float send = hi ? acc[v] : acc[v + 4];
        const float r = __shfl_xor_sync(FULL, send, 8);
        acc[v] = (hi ? acc[v + 4] : acc[v]) + r;
    }
#pragma unroll
    for (int v = 0; v < 2; ++v) {
        const bool hi = (lane & 4);
        const float send = hi ? acc[v] : acc[v + 2];
        const float r = __shfl_xor_sync(FULL, send, 4);
        acc[v] = (hi ? acc[v + 2] : acc[v]) + r;
    }
    {
        const bool hi = (lane & 2);
        const float send = hi ? acc[0] : acc[1];
        const float r = __shfl_xor_sync(FULL, send, 2);
        acc[0] = (hi ? acc[1] : acc[0]) + r;
    }
    acc[0] += __shfl_xor_sync(FULL, acc[0], 1);

    if ((lane & 1) == 0) {
        const int f = (lane >> 1) & 15;
        dst[f] = fmaf(0.5f, acc[0], -zi * DIAG[f]);
    }
}

__global__ void __launch_bounds__(128, 7) aev_radial_kernel(
    const float* __restrict__ dmat,   // [B, N, N]
    const float* __restrict__ zall,   // [B, N]
    float* __restrict__ out)          // [B, N, 16]
{
    const int warp_g = (blockIdx.x * blockDim.x + threadIdx.x) >> 5;  // 0..4095
    const int lane   = threadIdx.x & 31;
    const int b      = warp_g >> 8;
    const int i0     = warp_g & 255;

    const int wgA = b * NATOMS + i0;          // row A
    const int wgB = wgA + 256;                // row B (same batch)
    const float* __restrict__ rowA = dmat + (size_t)wgA * NATOMS;
    const float* __restrict__ rowB = dmat + (size_t)wgB * NATOMS;
    const float* __restrict__ zrow = zall + (size_t)b * NATOMS;

    float accA[NP], accB[NP];
#pragma unroll
    for (int p = 0; p < NP; ++p) { accA[p] = 0.0f; accB[p] = 0.0f; }

    // fused mainloop: both rows per iteration -> two independent dependency
    // chains per element slot (double ILP), shared z loads.
#pragma unroll
    for (int it = 0; it < 4; ++it) {
        const int j0 = it * 128 + lane * 4;
        const float4 da = *reinterpret_cast<const float4*>(rowA + j0);
        const float4 db = *reinterpret_cast<const float4*>(rowB + j0);
        const float4 zv = *reinterpret_cast<const float4*>(zrow + j0);

        aev_element(da.x, zv.x, accA);
        aev_element(db.x, zv.x, accB);
        aev_element(da.y, zv.y, accA);
        aev_element(db.y, zv.y, accB);
        aev_element(da.z, zv.z, accA);
        aev_element(db.z, zv.z, accB);
        aev_element(da.w, zv.w, accA);
        aev_element(db.w, zv.w, accB);
    }

    reduce_store(accA, zrow[i0],       out + (size_t)wgA * NP, lane);
    reduce_store(accB, zrow[i0 + 256], out + (size_t)wgB * NP, lane);
}

extern "C" void kernel_launch(void* const* d_in, const int* in_sizes, int n_in,
                              void* d_out, int out_size)
{
    const float* dmat = (const float*)d_in[0];   // [16, 512, 512] float32
    const float* zall = (const float*)d_in[1];   // [16, 512] float32
    float* out        = (float*)d_out;           // [16, 512, 16] float32

    // 1024 blocks x 128 threads = 4096 warps; each warp fuses 2 rows.
    // launch_bounds(128,7) caps regs at 73 -> 7 CTAs/SM -> single wave
    // (1024 = 6*148 + 136, 98.6% balanced).
    aev_radial_kernel<<<1024, 128>>>(dmat, zall, out);
}